// round 4
// baseline (speedup 1.0000x reference)
#include <cuda_runtime.h>

#define N_SAMPLES 65536
#define TPB 256
#define EPT 16
#define TILE (TPB * EPT)            // 4096 samples per block
#define CHUNKS (N_SAMPLES / TILE)   // 16 blocks per row

__device__ __forceinline__ double dcos_red(double x) {
    // cos(x) for |x| <= ~100 rad, abs err <= ~4e-9
    const double INV2PI = 0.15915494309189533576888376337251;
    const double TWOPI  = 6.283185307179586476925286766559;
    double q = rint(x * INV2PI);
    double r = fma(-q, TWOPI, x);          // |r| <= pi
    double u = r * r;
    double p = -1.5619206968586225e-16;    // -1/18!
    p = fma(p, u,  4.7794773323873853e-14);
    p = fma(p, u, -1.1470745597729725e-11);
    p = fma(p, u,  2.0876756987868098e-09);
    p = fma(p, u, -2.7557319223985893e-07);
    p = fma(p, u,  2.4801587301587302e-05);
    p = fma(p, u, -1.3888888888888889e-03);
    p = fma(p, u,  4.1666666666666664e-02);
    p = fma(p, u, -0.5);
    return fma(p, u, 1.0);
}

__device__ __forceinline__ float red2pi_d(double x) {
    const double INV2PI = 0.15915494309189533576888376337251;
    const double TWOPI  = 6.283185307179586476925286766559;
    double q = rint(x * INV2PI);
    return (float)fma(-q, TWOPI, x);
}

// XOR swizzle at float4 granularity: conflict-free for both the
// write pattern (v = 4*tid+g) and the read pattern (v = r*256+tid).
__device__ __forceinline__ int sw(int v) { return v ^ ((v >> 3) & 7); }

__global__ __launch_bounds__(TPB, 7)
void amfm_kernel(const float* __restrict__ theta_am,
                 const float* __restrict__ theta_fm,
                 const float* __restrict__ phase,
                 const float* __restrict__ phase_am,
                 const float* __restrict__ phase_fm,
                 const float* __restrict__ u_am_mi,
                 const float* __restrict__ u_fm_hz,
                 const float* __restrict__ u_f0_hz,
                 float* __restrict__ out)
{
    __shared__ double sh_base, sh_fm, sh_am, sh_mfm, sh_K2, sh_c2, sh_cosc2;
    __shared__ double sh_p0, sh_pfm, sh_pam;
    __shared__ float  sh_miam;
    __shared__ float4 tile4[TILE / 4];     // 16384 B

    const int bx    = blockIdx.x;
    const int row   = bx >> 4;             // / CHUNKS
    const int chunk = bx & (CHUNKS - 1);
    const int tid   = threadIdx.x;

    const float  TWOPI_F = 6.28318530717958647692f;  // fl32(2*pi)
    const double SR      = 44100.0;

    // ---- per-row setup, split across threads 0..2 ----
    if (tid == 0) {
        // AM chain
        float xa = __fadd_rn(__fmul_rn(theta_am[row], 4.0f), -1.0f);
        float am_hz = (float)exp2((double)xa);
        double wam = (double)__fmul_rn(TWOPI_F, am_hz);
        sh_am   = wam / SR;
        sh_pam  = (double)__fmul_rn(TWOPI_F, phase_am[row]);
        sh_miam = u_am_mi[row];
    } else if (tid == 1) {
        // FM chain
        float xf = __fadd_rn(__fmul_rn(u_fm_hz[row], 4.0f), -1.0f);
        float fm_hz = (float)exp2((double)xf);
        double wfm  = (double)__fmul_rn(TWOPI_F, fm_hz);
        double dfm  = wfm / SR;                      // fm rad/sample
        double half = 0.5 * dfm;
        double h2   = half * half;
        double sinh = half * fma(h2, fma(h2, (1.0/120.0), -(1.0/6.0)), 1.0);
        double K2   = 0.5 / sinh;
        double pfm  = (double)__fmul_rn(TWOPI_F, phase_fm[row]);
        double c2   = pfm - half;
        sh_fm  = dfm;
        sh_K2  = K2;
        sh_c2  = c2;
        sh_pfm = pfm;
        sh_cosc2 = dcos_red(c2);
    } else if (tid == 2) {
        // carrier chain
        double lgl = log2(32.7);
        double lgh = log2(523.25);
        float x0 = __fadd_rn(__fmul_rn(u_f0_hz[row], (float)(lgh - lgl)), (float)lgl);
        float f0_hz = (float)exp2((double)x0);
        double w0 = (double)__fmul_rn(TWOPI_F, f0_hz);
        sh_base = w0 / SR;                           // carrier rad/sample
        sh_mfm  = w0 * (double)theta_fm[row] / SR;   // fm depth rad/sample
        sh_p0   = (double)__fmul_rn(TWOPI_F, phase[row]);
    }
    __syncthreads();

    // ---- per-thread anchors (double, short) ----
    const double dfm   = sh_fm;
    const double n     = (double)(chunk * TILE + tid * EPT);
    const double mfmK2 = sh_mfm * sh_K2;

    // carrier anchor: exclusive prefix of modulation via closed form
    //   S(n) = K2*(cos(c2) - cos(n*dfm + c2))
    double costh = dcos_red(fma(n, dfm, sh_c2));
    double off   = fma(sh_base, n, sh_p0) + mfmK2 * (sh_cosc2 - costh);
    float  s     = red2pi_d(off);

    // modulator phase anchors (drift over 16 samples <= 0.019 rad -> no wrap)
    float ft = red2pi_d(fma(n, dfm,   sh_pfm));
    float at = red2pi_d(fma(n, sh_am, sh_pam));

    const float fmtf  = (float)dfm;
    const float amtf  = (float)sh_am;
    const float basef = (float)sh_base;
    const float mfmf  = (float)sh_mfm;
    const float miamf = sh_miam;
    const float PI_F  = 3.14159265358979323846f;

    // ---- synthesize 16 samples into swizzled smem (conflict-free STS.128) ----
    #pragma unroll
    for (int g = 0; g < 4; g++) {
        float v[4];
        #pragma unroll
        for (int j = 0; j < 4; j++) {
            float sf = __sinf(ft);   ft += fmtf;          // fm modulator
            s += fmaf(mfmf, sf, basef);                   // inclusive phase update
            s -= (s > PI_F) ? TWOPI_F : 0.0f;             // wrap
            float xc = __sinf(s);                         // carrier
            float sa = __sinf(at);   at += amtf;          // am modulator
            v[j] = (0.5f * xc) * fmaf(miamf, sa, 1.0f);
        }
        tile4[sw(4 * tid + g)] = make_float4(v[0], v[1], v[2], v[3]);
    }
    __syncthreads();

    // ---- coalesced writeback: warp writes 512B contiguous per STG.128 ----
    float4* __restrict__ o4 =
        (float4*)(out + (size_t)row * N_SAMPLES + chunk * TILE);
    #pragma unroll
    for (int r = 0; r < 4; r++) {
        o4[r * 256 + tid] = tile4[sw(r * 256 + tid)];
    }
}

extern "C" void kernel_launch(void* const* d_in, const int* in_sizes, int n_in,
                              void* d_out, int out_size) {
    const int B = in_sizes[0];   // 256 rows
    amfm_kernel<<<B * CHUNKS, TPB>>>(
        (const float*)d_in[0],   // theta_am_0to1
        (const float*)d_in[1],   // theta_fm_0to1
        (const float*)d_in[2],   // phase
        (const float*)d_in[3],   // phase_am
        (const float*)d_in[4],   // phase_fm
        (const float*)d_in[5],   // u_am_mi
        (const float*)d_in[6],   // u_fm_hz
        (const float*)d_in[7],   // u_f0_hz
        (float*)d_out);
}

// round 5
// speedup vs baseline: 1.3069x; 1.3069x over previous
#include <cuda_runtime.h>

#define N_SAMPLES 65536
#define TPB 256
#define EPT 16
#define TILE (TPB * EPT)            // 4096 samples per block
#define CHUNKS (N_SAMPLES / TILE)   // 16 blocks per row

#define TWOPI_F 6.28318530717958647692f   /* fl32(2*pi) */
#define PI_F    3.14159265358979323846f
#define INV2PI_D 0.15915494309189533576888376337251

__device__ __forceinline__ float2 ds_from_d(double x) {
    float h = (float)x;
    return make_float2(h, (float)(x - (double)h));
}

// frac(c*n + p) in turns via double-single fp32 arithmetic.
// n is an exact fp32 integer. Result (hi,lo), hi in [-0.5, 0.5]+eps.
__device__ __forceinline__ float2 ds_anchor(float2 c, float2 p, float n) {
    float ph = __fmul_rn(c.x, n);
    float pe = fmaf(c.x, n, -ph);            // exact twoProd residual
    float pl = fmaf(c.y, n, pe);
    float s  = ph + p.x;                     // two-sum
    float bb = s - ph;
    float er = (ph - (s - bb)) + (p.x - bb);
    float lo = er + pl + p.y;
    float q  = rintf(s);
    float rh = s - q;                        // exact
    float t  = rh + lo;
    float tl = lo - (t - rh);
    return make_float2(t, tl);
}

// cos(2*pi*(x.hi+x.lo)) for |x.hi| <= 0.5+eps; abs err ~1.2e-7 worst
__device__ __forceinline__ float cos2pi(float2 x) {
    float k = rintf(2.0f * x.x);             // quadrant: k in {-1,0,1}
    float z = (x.x - 0.5f * k) + x.y;        // |z| <= 0.25+eps, exact sub
    float u = z * z;
    float pp = fmaf(7.9033069f, u, -26.4262561f);
    pp = fmaf(pp, u,  60.2446416f);
    pp = fmaf(pp, u, -85.4568172f);
    pp = fmaf(pp, u,  64.9393940f);
    pp = fmaf(pp, u, -19.7392088f);
    float c = fmaf(pp, u, 1.0f);
    float sgn = fmaf(-2.0f, fabsf(k), 1.0f); // +1 if k==0 else -1
    return c * sgn;
}

// XOR swizzle at float4 granularity: conflict-free for writes (4*tid+g)
// and reads (r*256+tid).
__device__ __forceinline__ int sw(int v) { return v ^ ((v >> 3) & 7); }

__global__ __launch_bounds__(TPB, 6)
void amfm_kernel(const float* __restrict__ theta_am,
                 const float* __restrict__ theta_fm,
                 const float* __restrict__ phase,
                 const float* __restrict__ phase_am,
                 const float* __restrict__ phase_fm,
                 const float* __restrict__ u_am_mi,
                 const float* __restrict__ u_fm_hz,
                 const float* __restrict__ u_f0_hz,
                 float* __restrict__ out)
{
    __shared__ float2 sh_base_t, sh_dfm_t, sh_am_t, sh_p0_t, sh_pfm_t, sh_pam_t;
    __shared__ float2 sh_c2_t, sh_mk, sh_cosc2;
    __shared__ float  sh_basef, sh_mfmf, sh_miam, sh_sdf, sh_cdf, sh_sda, sh_cda;
    __shared__ double sh_K2d, sh_mfmd;
    __shared__ float4 tile4[TILE / 4];       // 16 KB

    const int bx    = blockIdx.x;
    const int row   = bx >> 4;               // / CHUNKS
    const int chunk = bx & (CHUNKS - 1);
    const int tid   = threadIdx.x;
    const double SR = 44100.0;

    // ---- per-row setup (DP lives ONLY here, split over threads 0..2) ----
    if (tid == 0) {
        // AM chain
        float xa = __fadd_rn(__fmul_rn(theta_am[row], 4.0f), -1.0f);
        float am_hz = (float)exp2((double)xa);
        double wam = (double)__fmul_rn(TWOPI_F, am_hz);
        double am_rad = wam / SR;
        sh_am_t  = ds_from_d(am_rad * INV2PI_D);
        sh_pam_t = ds_from_d((double)__fmul_rn(TWOPI_F, phase_am[row]) * INV2PI_D);
        sh_miam  = u_am_mi[row];
        double sd_, cd_;
        sincos(am_rad, &sd_, &cd_);
        sh_sda = (float)sd_;  sh_cda = (float)cd_;
    } else if (tid == 1) {
        // FM chain
        float xf = __fadd_rn(__fmul_rn(u_fm_hz[row], 4.0f), -1.0f);
        float fm_hz = (float)exp2((double)xf);
        double wfm = (double)__fmul_rn(TWOPI_F, fm_hz);
        double dfm = wfm / SR;                          // fm rad/sample
        double half = 0.5 * dfm;
        double K2 = 0.5 / sin(half);
        double pfm = (double)__fmul_rn(TWOPI_F, phase_fm[row]);
        double c2 = pfm - half;
        sh_dfm_t = ds_from_d(dfm * INV2PI_D);
        sh_pfm_t = ds_from_d(pfm * INV2PI_D);
        sh_c2_t  = ds_from_d(c2 * INV2PI_D);
        sh_cosc2 = ds_from_d(cos(c2));
        sh_K2d = K2;
        double sd_, cd_;
        sincos(dfm, &sd_, &cd_);
        sh_sdf = (float)sd_;  sh_cdf = (float)cd_;
    } else if (tid == 2) {
        // carrier chain
        double lgl = log2(32.7);
        double lgh = log2(523.25);
        float x0 = __fadd_rn(__fmul_rn(u_f0_hz[row], (float)(lgh - lgl)), (float)lgl);
        float f0_hz = (float)exp2((double)x0);
        double w0 = (double)__fmul_rn(TWOPI_F, f0_hz);
        double base = w0 / SR;                          // carrier rad/sample
        double mfm  = w0 * (double)theta_fm[row] / SR;  // fm depth rad/sample
        sh_base_t = ds_from_d(base * INV2PI_D);
        sh_p0_t   = ds_from_d((double)__fmul_rn(TWOPI_F, phase[row]) * INV2PI_D);
        sh_basef = (float)base;
        sh_mfmf  = (float)mfm;
        sh_mfmd  = mfm;
    }
    __syncthreads();
    if (tid == 0) {
        sh_mk = ds_from_d(sh_mfmd * sh_K2d * INV2PI_D); // modulation gain, turns
    }
    __syncthreads();

    const float2 base_t = sh_base_t, dfm_t = sh_dfm_t, am_t = sh_am_t;
    const float2 p0_t = sh_p0_t, pfm_t = sh_pfm_t, pam_t = sh_pam_t;
    const float2 c2_t = sh_c2_t, mk = sh_mk, cosc2 = sh_cosc2;
    const float basef = sh_basef, mfmf = sh_mfmf, miamf = sh_miam;
    const float sdf = sh_sdf, cdf = sh_cdf, sda = sh_sda, cda = sh_cda;

    const float n = (float)(chunk * TILE + tid * EPT);  // exact integer

    // ---- carrier anchor: off = p0 + base*n + mk*(cos(c2) - cos(n*dfm + c2)) ----
    float2 th = ds_anchor(dfm_t, c2_t, n);
    float cth = cos2pi(th);
    // diff = cosc2 - cth   (two-sum, keep DS)
    float dh = cosc2.x - cth;
    float db = dh - cosc2.x;
    float de = (cosc2.x - (dh - db)) + ((-cth) - db);
    float dl = de + cosc2.y;
    // mod = mk * diff
    float mh = __fmul_rn(mk.x, dh);
    float me = fmaf(mk.x, dh, -mh);
    float ml = fmaf(mk.y, dh, fmaf(mk.x, dl, me));
    // g = base*n
    float gh = __fmul_rn(base_t.x, n);
    float ge = fmaf(base_t.x, n, -gh);
    float gl = fmaf(base_t.y, n, ge);
    // sum (gh,gl) + p0 + (mh,ml), then frac
    float s1 = gh + p0_t.x;
    float b1 = s1 - gh;
    float e1 = (gh - (s1 - b1)) + (p0_t.x - b1);
    float s2 = s1 + mh;
    float b2 = s2 - s1;
    float e2 = (s1 - (s2 - b2)) + (mh - b2);
    float lo = gl + p0_t.y + e1 + ml + e2;
    float q  = rintf(s2);
    float rh = s2 - q;
    float s  = TWOPI_F * (rh + lo);              // carrier phase, radians

    // ---- modulator anchors + rotation state ----
    float2 ftt = ds_anchor(dfm_t, pfm_t, n);
    float fta = TWOPI_F * (ftt.x + ftt.y);
    float sf = __sinf(fta), cf = __cosf(fta);
    float2 att = ds_anchor(am_t, pam_t, n);
    float ata = TWOPI_F * (att.x + att.y);
    float sa = __sinf(ata), ca = __cosf(ata);

    // ---- synthesize 16 samples into swizzled smem ----
    #pragma unroll
    for (int g = 0; g < 4; g++) {
        float v[4];
        #pragma unroll
        for (int j = 0; j < 4; j++) {
            s += fmaf(mfmf, sf, basef);              // inclusive phase update
            s -= (s > PI_F) ? TWOPI_F : 0.0f;        // wrap
            float xc = __sinf(s);                    // carrier (only MUFU in loop)
            v[j] = (0.5f * xc) * fmaf(miamf, sa, 1.0f);
            // rotate fm modulator by dfm
            float nsf = fmaf(cf, sdf, sf * cdf);
            float ncf = fmaf(cf, cdf, -(sf * sdf));
            sf = nsf; cf = ncf;
            // rotate am modulator by dam
            float nsa = fmaf(ca, sda, sa * cda);
            float nca = fmaf(ca, cda, -(sa * sda));
            sa = nsa; ca = nca;
        }
        tile4[sw(4 * tid + g)] = make_float4(v[0], v[1], v[2], v[3]);
    }
    __syncthreads();

    // ---- coalesced writeback: warp writes 512B contiguous per STG.128 ----
    float4* __restrict__ o4 =
        (float4*)(out + (size_t)row * N_SAMPLES + chunk * TILE);
    #pragma unroll
    for (int r = 0; r < 4; r++) {
        o4[r * 256 + tid] = tile4[sw(r * 256 + tid)];
    }
}

extern "C" void kernel_launch(void* const* d_in, const int* in_sizes, int n_in,
                              void* d_out, int out_size) {
    const int B = in_sizes[0];   // 256 rows
    amfm_kernel<<<B * CHUNKS, TPB>>>(
        (const float*)d_in[0],   // theta_am_0to1
        (const float*)d_in[1],   // theta_fm_0to1
        (const float*)d_in[2],   // phase
        (const float*)d_in[3],   // phase_am
        (const float*)d_in[4],   // phase_fm
        (const float*)d_in[5],   // u_am_mi
        (const float*)d_in[6],   // u_fm_hz
        (const float*)d_in[7],   // u_f0_hz
        (float*)d_out);
}

// round 6
// speedup vs baseline: 4.1754x; 3.1950x over previous
#include <cuda_runtime.h>

#define N_SAMPLES 65536
#define TPB 256
#define EPT 16
#define TILE (TPB * EPT)            // 4096 samples per block
#define CHUNKS (N_SAMPLES / TILE)   // 16 blocks per row
#define MAXB 512

#define TWOPI_F 6.28318530717958647692f   /* fl32(2*pi) */
#define PI_F    3.14159265358979323846f
#define INV2PI_D 0.15915494309189533576888376337251

struct Row {
    float2 base_t, p0_t;          // carrier slope/phase (turns)
    float2 dfm_t, pfm_t, c2_t;    // fm slope/phase/c2 (turns)
    float2 cosc2;                 // cos(c2) value, double-single
    float2 am_t, pam_t;           // am slope/phase (turns)
    float2 mk;                    // mfm*K2/(2pi)  (turns)
    float  basef, mfmf, fmtf, amtf, half_miam, pad;
};
__device__ Row g_rows[MAXB];

__device__ __forceinline__ float2 ds_from_d(double x) {
    float h = (float)x;
    return make_float2(h, (float)(x - (double)h));
}

__device__ __forceinline__ double dcos_red(double x) {
    // cos(x), |x| <= ~40, abs err ~4e-9 (setup only)
    const double TWOPI_D = 6.283185307179586476925286766559;
    double q = rint(x * INV2PI_D);
    double r = fma(-q, TWOPI_D, x);
    double u = r * r;
    double p = -1.5619206968586225e-16;
    p = fma(p, u,  4.7794773323873853e-14);
    p = fma(p, u, -1.1470745597729725e-11);
    p = fma(p, u,  2.0876756987868098e-09);
    p = fma(p, u, -2.7557319223985893e-07);
    p = fma(p, u,  2.4801587301587302e-05);
    p = fma(p, u, -1.3888888888888889e-03);
    p = fma(p, u,  4.1666666666666664e-02);
    p = fma(p, u, -0.5);
    return fma(p, u, 1.0);
}

// ---- setup: one block (32 threads) per row; ALL fp64 lives here ----
__global__ void setup_kernel(const float* __restrict__ theta_am,
                             const float* __restrict__ theta_fm,
                             const float* __restrict__ phase,
                             const float* __restrict__ phase_am,
                             const float* __restrict__ phase_fm,
                             const float* __restrict__ u_am_mi,
                             const float* __restrict__ u_fm_hz,
                             const float* __restrict__ u_f0_hz)
{
    const int row = blockIdx.x;
    const int tid = threadIdx.x;
    const double INV_SR = 1.0 / 44100.0;
    __shared__ double sh_K2, sh_mfm;
    Row* r = &g_rows[row];

    if (tid == 0) {
        // AM chain
        float xa = __fadd_rn(__fmul_rn(theta_am[row], 4.0f), -1.0f);
        float am_hz = (float)exp2((double)xa);
        double am_rad = (double)__fmul_rn(TWOPI_F, am_hz) * INV_SR;
        r->am_t  = ds_from_d(am_rad * INV2PI_D);
        r->pam_t = ds_from_d((double)__fmul_rn(TWOPI_F, phase_am[row]) * INV2PI_D);
        r->amtf  = (float)am_rad;
        r->half_miam = 0.5f * u_am_mi[row];
    } else if (tid == 1) {
        // FM chain
        float xf = __fadd_rn(__fmul_rn(u_fm_hz[row], 4.0f), -1.0f);
        float fm_hz = (float)exp2((double)xf);
        double dfm = (double)__fmul_rn(TWOPI_F, fm_hz) * INV_SR; // rad/sample
        double half = 0.5 * dfm;
        double h2 = half * half;
        double sinh = half * fma(h2, fma(h2, (1.0/120.0), -(1.0/6.0)), 1.0);
        sh_K2 = 0.5 / sinh;
        double pfm = (double)__fmul_rn(TWOPI_F, phase_fm[row]);
        double c2  = pfm - half;
        r->dfm_t = ds_from_d(dfm * INV2PI_D);
        r->pfm_t = ds_from_d(pfm * INV2PI_D);
        r->c2_t  = ds_from_d(c2 * INV2PI_D);
        r->cosc2 = ds_from_d(dcos_red(c2));
        r->fmtf  = (float)dfm;
    } else if (tid == 2) {
        // carrier chain
        double lgl = log2(32.7);
        double lgh = log2(523.25);
        float x0 = __fadd_rn(__fmul_rn(u_f0_hz[row], (float)(lgh - lgl)), (float)lgl);
        float f0_hz = (float)exp2((double)x0);
        double base = (double)__fmul_rn(TWOPI_F, f0_hz) * INV_SR; // rad/sample
        double mfm  = base * (double)theta_fm[row];               // fm depth rad/sample
        sh_mfm = mfm;
        r->base_t = ds_from_d(base * INV2PI_D);
        r->p0_t   = ds_from_d((double)__fmul_rn(TWOPI_F, phase[row]) * INV2PI_D);
        r->basef = (float)base;
        r->mfmf  = (float)mfm;
    }
    __syncthreads();
    if (tid == 0) {
        r->mk = ds_from_d(sh_mfm * sh_K2 * INV2PI_D);
    }
}

// frac(c*n + p) in turns via double-single fp32 arithmetic.
__device__ __forceinline__ float2 ds_anchor(float2 c, float2 p, float n) {
    float ph = __fmul_rn(c.x, n);
    float pe = fmaf(c.x, n, -ph);            // exact twoProd residual
    float pl = fmaf(c.y, n, pe);
    float s  = ph + p.x;                     // two-sum
    float bb = s - ph;
    float er = (ph - (s - bb)) + (p.x - bb);
    float lo = er + pl + p.y;
    float q  = rintf(s);
    float rh = s - q;                        // exact
    float t  = rh + lo;
    float tl = lo - (t - rh);
    return make_float2(t, tl);
}

// cos(2*pi*(x.hi+x.lo)) for |x.hi| <= 0.5+eps; abs err ~1.2e-7
__device__ __forceinline__ float cos2pi(float2 x) {
    float k = rintf(2.0f * x.x);
    float z = (x.x - 0.5f * k) + x.y;
    float u = z * z;
    float pp = fmaf(7.9033069f, u, -26.4262561f);
    pp = fmaf(pp, u,  60.2446416f);
    pp = fmaf(pp, u, -85.4568172f);
    pp = fmaf(pp, u,  64.9393940f);
    pp = fmaf(pp, u, -19.7392088f);
    float c = fmaf(pp, u, 1.0f);
    float sgn = fmaf(-2.0f, fabsf(k), 1.0f);
    return c * sgn;
}

// XOR swizzle at float4 granularity (conflict-free both phases)
__device__ __forceinline__ int sw(int v) { return v ^ ((v >> 3) & 7); }

__global__ __launch_bounds__(TPB, 6)
void amfm_main(float* __restrict__ out)
{
    __shared__ float4 tile4[TILE / 4];       // 16 KB

    const int bx    = blockIdx.x;
    const int row   = bx >> 4;               // / CHUNKS
    const int chunk = bx & (CHUNKS - 1);
    const int tid   = threadIdx.x;

    const Row* __restrict__ rp = &g_rows[row];
    const float2 base_t = rp->base_t, p0_t = rp->p0_t;
    const float2 dfm_t = rp->dfm_t, pfm_t = rp->pfm_t, c2_t = rp->c2_t;
    const float2 cosc2 = rp->cosc2, am_t = rp->am_t, pam_t = rp->pam_t;
    const float2 mk = rp->mk;
    const float basef = rp->basef, mfmf = rp->mfmf, fmtf = rp->fmtf,
                amtf = rp->amtf, hmiam = rp->half_miam;

    const float n = (float)(chunk * TILE + tid * EPT);  // exact integer

    // ---- carrier anchor: off = p0 + base*n + mk*(cos(c2) - cos(n*dfm + c2)) ----
    float2 th = ds_anchor(dfm_t, c2_t, n);
    float cth = cos2pi(th);
    float dh = cosc2.x - cth;                // two-sum diff, keep DS
    float db = dh - cosc2.x;
    float de = (cosc2.x - (dh - db)) + ((-cth) - db);
    float dl = de + cosc2.y;
    float mh = __fmul_rn(mk.x, dh);          // mod = mk * diff
    float me = fmaf(mk.x, dh, -mh);
    float ml = fmaf(mk.y, dh, fmaf(mk.x, dl, me));
    float gh = __fmul_rn(base_t.x, n);       // g = base*n
    float ge = fmaf(base_t.x, n, -gh);
    float gl = fmaf(base_t.y, n, ge);
    float s1 = gh + p0_t.x;                  // sum + frac
    float b1 = s1 - gh;
    float e1 = (gh - (s1 - b1)) + (p0_t.x - b1);
    float s2 = s1 + mh;
    float b2 = s2 - s1;
    float e2 = (s1 - (s2 - b2)) + (mh - b2);
    float lo = gl + p0_t.y + e1 + ml + e2;
    float q  = rintf(s2);
    float rh = s2 - q;
    float s  = TWOPI_F * (rh + lo);          // carrier phase, radians

    // ---- modulator phase anchors (radians; drift over 16 steps ~ 0.018 rad) ----
    float2 ftt = ds_anchor(dfm_t, pfm_t, n);
    float ft = TWOPI_F * (ftt.x + ftt.y);
    float2 att = ds_anchor(am_t, pam_t, n);
    float at = TWOPI_F * (att.x + att.y);

    // ---- synthesize 16 samples into swizzled smem ----
    #pragma unroll
    for (int g = 0; g < 4; g++) {
        float v[4];
        #pragma unroll
        for (int j = 0; j < 4; j++) {
            float sf = __sinf(ft);   ft += fmtf;      // fm modulator
            s += fmaf(mfmf, sf, basef);               // inclusive phase update
            s -= (s > PI_F) ? TWOPI_F : 0.0f;         // wrap
            float xc = __sinf(s);                     // carrier
            float sa = __sinf(at);   at += amtf;      // am modulator
            v[j] = xc * fmaf(hmiam, sa, 0.5f);        // 0.5*(1+mi*sa)*sin
        }
        tile4[sw(4 * tid + g)] = make_float4(v[0], v[1], v[2], v[3]);
    }
    __syncthreads();

    // ---- coalesced writeback: warp writes 512B contiguous per STG.128 ----
    float4* __restrict__ o4 =
        (float4*)(out + (size_t)row * N_SAMPLES + chunk * TILE);
    #pragma unroll
    for (int r = 0; r < 4; r++) {
        o4[r * 256 + tid] = tile4[sw(r * 256 + tid)];
    }
}

extern "C" void kernel_launch(void* const* d_in, const int* in_sizes, int n_in,
                              void* d_out, int out_size) {
    const int B = in_sizes[0];   // 256 rows
    setup_kernel<<<B, 32>>>(
        (const float*)d_in[0],   // theta_am_0to1
        (const float*)d_in[1],   // theta_fm_0to1
        (const float*)d_in[2],   // phase
        (const float*)d_in[3],   // phase_am
        (const float*)d_in[4],   // phase_fm
        (const float*)d_in[5],   // u_am_mi
        (const float*)d_in[6],   // u_fm_hz
        (const float*)d_in[7]);  // u_f0_hz
    amfm_main<<<B * CHUNKS, TPB>>>((float*)d_out);
}

// round 7
// speedup vs baseline: 5.2724x; 1.2627x over previous
#include <cuda_runtime.h>

#define N_SAMPLES 65536
#define TPB 256
#define EPT 16
#define TILE (TPB * EPT)            // 4096 samples per block
#define CHUNKS (N_SAMPLES / TILE)   // 16 blocks per row
#define MAXB 512

#define TWOPI_F 6.28318530717958647692f   /* fl32(2*pi) */
#define INV2PI_D 0.15915494309189533576888376337251

struct Row {
    float2 base_t, p0_t;          // carrier slope/phase (turns, DS)
    float2 dfm_t, pfm_t, c2_t;    // fm slope/phase/c2 (turns, DS)
    float2 cosc2;                 // cos(c2), DS
    float2 mfm_t;                 // fm depth (rad/sample, DS)
    float2 k2t_t;                 // K2/(2pi), DS
    float  basef, mfmf, fmtf;     // rad/sample fp32
    float  amt_turns, pam_turns, amtf_rad, half_miam, pad;
};
__device__ Row g_rows[MAXB];

__device__ __forceinline__ float2 ds_from_d(double x) {
    float h = (float)x;
    return make_float2(h, (float)(x - (double)h));
}

__device__ __forceinline__ double dcos_red(double x) {
    // cos(x), |x| <= ~40, abs err ~4e-9 (setup only)
    const double TWOPI_D = 6.283185307179586476925286766559;
    double q = rint(x * INV2PI_D);
    double r = fma(-q, TWOPI_D, x);
    double u = r * r;
    double p = -1.5619206968586225e-16;
    p = fma(p, u,  4.7794773323873853e-14);
    p = fma(p, u, -1.1470745597729725e-11);
    p = fma(p, u,  2.0876756987868098e-09);
    p = fma(p, u, -2.7557319223985893e-07);
    p = fma(p, u,  2.4801587301587302e-05);
    p = fma(p, u, -1.3888888888888889e-03);
    p = fma(p, u,  4.1666666666666664e-02);
    p = fma(p, u, -0.5);
    return fma(p, u, 1.0);
}

// ---- setup: 24 single-warp blocks; block = (chain type, 32-row group).
// All FP64 lives here, spread across 24 SMs, SIMT over rows (no divergence).
__global__ void setup_kernel(const float* __restrict__ theta_am,
                             const float* __restrict__ theta_fm,
                             const float* __restrict__ phase,
                             const float* __restrict__ phase_am,
                             const float* __restrict__ phase_fm,
                             const float* __restrict__ u_am_mi,
                             const float* __restrict__ u_fm_hz,
                             const float* __restrict__ u_f0_hz,
                             int B)
{
    const int chain = blockIdx.x >> 3;                    // 0,1,2
    const int row   = ((blockIdx.x & 7) << 5) + threadIdx.x;
    if (row >= B) return;
    const double INV_SR = 1.0 / 44100.0;
    Row* r = &g_rows[row];

    if (chain == 0) {
        // AM chain (fp32-precision targets only)
        float xa = __fadd_rn(__fmul_rn(theta_am[row], 4.0f), -1.0f);
        float am_hz = (float)exp2((double)xa);
        double am_rad = (double)__fmul_rn(TWOPI_F, am_hz) * INV_SR;
        r->amt_turns = (float)(am_rad * INV2PI_D);
        r->pam_turns = (float)((double)__fmul_rn(TWOPI_F, phase_am[row]) * INV2PI_D);
        r->amtf_rad  = (float)am_rad;
        r->half_miam = 0.5f * u_am_mi[row];
    } else if (chain == 1) {
        // FM chain
        float xf = __fadd_rn(__fmul_rn(u_fm_hz[row], 4.0f), -1.0f);
        float fm_hz = (float)exp2((double)xf);
        double dfm = (double)__fmul_rn(TWOPI_F, fm_hz) * INV_SR;  // rad/sample
        double half = 0.5 * dfm;
        double h2 = half * half;
        double sinh = half * fma(h2, fma(h2, (1.0/120.0), -(1.0/6.0)), 1.0);
        double K2 = 0.5 / sinh;
        double pfm = (double)__fmul_rn(TWOPI_F, phase_fm[row]);
        double c2  = pfm - half;
        r->dfm_t  = ds_from_d(dfm * INV2PI_D);
        r->pfm_t  = ds_from_d(pfm * INV2PI_D);
        r->c2_t   = ds_from_d(c2 * INV2PI_D);
        r->cosc2  = ds_from_d(dcos_red(c2));
        r->k2t_t  = ds_from_d(K2 * INV2PI_D);
        r->fmtf   = (float)dfm;
    } else {
        // carrier chain
        double lgl = log2(32.7);
        double lgh = log2(523.25);
        float x0 = __fadd_rn(__fmul_rn(u_f0_hz[row], (float)(lgh - lgl)), (float)lgl);
        float f0_hz = (float)exp2((double)x0);
        double base = (double)__fmul_rn(TWOPI_F, f0_hz) * INV_SR;  // rad/sample
        double mfm  = base * (double)theta_fm[row];                // rad/sample
        r->base_t = ds_from_d(base * INV2PI_D);
        r->p0_t   = ds_from_d((double)__fmul_rn(TWOPI_F, phase[row]) * INV2PI_D);
        r->mfm_t  = ds_from_d(mfm);
        r->basef  = (float)base;
        r->mfmf   = (float)mfm;
    }
}

// frac(c*n + p) in turns via double-single fp32 arithmetic.
__device__ __forceinline__ float2 ds_anchor(float2 c, float2 p, float n) {
    float ph = __fmul_rn(c.x, n);
    float pe = fmaf(c.x, n, -ph);            // exact twoProd residual
    float pl = fmaf(c.y, n, pe);
    float s  = ph + p.x;                     // two-sum
    float bb = s - ph;
    float er = (ph - (s - bb)) + (p.x - bb);
    float lo = er + pl + p.y;
    float q  = rintf(s);
    float rh = s - q;                        // exact
    float t  = rh + lo;
    float tl = lo - (t - rh);
    return make_float2(t, tl);
}

// cos(2*pi*(x.hi+x.lo)) for |x.hi| <= 0.5+eps; abs err ~1.2e-7
__device__ __forceinline__ float cos2pi(float2 x) {
    float k = rintf(2.0f * x.x);
    float z = (x.x - 0.5f * k) + x.y;
    float u = z * z;
    float pp = fmaf(7.9033069f, u, -26.4262561f);
    pp = fmaf(pp, u,  60.2446416f);
    pp = fmaf(pp, u, -85.4568172f);
    pp = fmaf(pp, u,  64.9393940f);
    pp = fmaf(pp, u, -19.7392088f);
    float c = fmaf(pp, u, 1.0f);
    float sgn = fmaf(-2.0f, fabsf(k), 1.0f);
    return c * sgn;
}

// XOR swizzle at float4 granularity (conflict-free both phases)
__device__ __forceinline__ int sw(int v) { return v ^ ((v >> 3) & 7); }

__global__ __launch_bounds__(TPB, 6)
void amfm_main(float* __restrict__ out)
{
    __shared__ float4 tile4[TILE / 4];       // 16 KB

    const int bx    = blockIdx.x;
    const int row   = bx >> 4;               // / CHUNKS
    const int chunk = bx & (CHUNKS - 1);
    const int tid   = threadIdx.x;

    const Row* __restrict__ rp = &g_rows[row];
    const float2 base_t = rp->base_t, p0_t = rp->p0_t;
    const float2 dfm_t = rp->dfm_t, pfm_t = rp->pfm_t, c2_t = rp->c2_t;
    const float2 cosc2 = rp->cosc2, mfm_t = rp->mfm_t, k2t_t = rp->k2t_t;
    const float basef = rp->basef, mfmf = rp->mfmf, fmtf = rp->fmtf;
    const float amt_turns = rp->amt_turns, pam_turns = rp->pam_turns,
                amtf = rp->amtf_rad, hmiam = rp->half_miam;

    // mk = mfm * K2/(2pi)  (DS multiply; |mk| <= ~167 turns, rel err ~2^-40)
    float mkh = __fmul_rn(mfm_t.x, k2t_t.x);
    float mke = fmaf(mfm_t.x, k2t_t.x, -mkh);
    float mkl = fmaf(mfm_t.x, k2t_t.y, fmaf(mfm_t.y, k2t_t.x, mke));

    const float n = (float)(chunk * TILE + tid * EPT);   // exact integer

    // ---- carrier anchor: off = p0 + base*n + mk*(cos(c2) - cos(n*dfm + c2)) ----
    float2 th = ds_anchor(dfm_t, c2_t, n);
    float cth = cos2pi(th);
    float dh = cosc2.x - cth;                // two-sum diff, keep DS
    float db = dh - cosc2.x;
    float de = (cosc2.x - (dh - db)) + ((-cth) - db);
    float dl = de + cosc2.y;
    float mh = __fmul_rn(mkh, dh);           // mod = mk * diff
    float me = fmaf(mkh, dh, -mh);
    float ml = fmaf(mkl, dh, fmaf(mkh, dl, me));
    float gh = __fmul_rn(base_t.x, n);       // g = base*n
    float ge = fmaf(base_t.x, n, -gh);
    float gl = fmaf(base_t.y, n, ge);
    float s1 = gh + p0_t.x;                  // sum + frac
    float b1 = s1 - gh;
    float e1 = (gh - (s1 - b1)) + (p0_t.x - b1);
    float s2 = s1 + mh;
    float b2 = s2 - s1;
    float e2 = (s1 - (s2 - b2)) + (mh - b2);
    float lo = gl + p0_t.y + e1 + ml + e2;
    float q  = rintf(s2);
    float rh = s2 - q;
    float s  = TWOPI_F * (rh + lo);          // carrier phase, radians, |s|<~3.2

    // ---- fm modulator anchor (DS; error here is K2-amplified) ----
    float2 ftt = ds_anchor(dfm_t, pfm_t, n);
    float ft = TWOPI_F * (ftt.x + ftt.y);

    // ---- am modulator anchor (plain fp32 is ample: affects output ~mi*err) ----
    float ap = fmaf(amt_turns, n, pam_turns);
    float at = TWOPI_F * (ap - rintf(ap));

    // ---- synthesize 16 samples into swizzled smem ----
    // No carrier wrap: |s| grows to <= ~5.7 rad; __sinf fine there.
    #pragma unroll
    for (int g = 0; g < 4; g++) {
        float v[4];
        #pragma unroll
        for (int j = 0; j < 4; j++) {
            float sf = __sinf(ft);   ft += fmtf;      // fm modulator
            s += fmaf(mfmf, sf, basef);               // inclusive phase update
            float xc = __sinf(s);                     // carrier
            float sa = __sinf(at);   at += amtf;      // am modulator
            v[j] = xc * fmaf(hmiam, sa, 0.5f);        // 0.5*(1+mi*sa)*sin
        }
        tile4[sw(4 * tid + g)] = make_float4(v[0], v[1], v[2], v[3]);
    }
    __syncthreads();

    // ---- coalesced writeback: warp writes 512B contiguous per STG.128 ----
    float4* __restrict__ o4 =
        (float4*)(out + (size_t)row * N_SAMPLES + chunk * TILE);
    #pragma unroll
    for (int r = 0; r < 4; r++) {
        o4[r * 256 + tid] = tile4[sw(r * 256 + tid)];
    }
}

extern "C" void kernel_launch(void* const* d_in, const int* in_sizes, int n_in,
                              void* d_out, int out_size) {
    const int B = in_sizes[0];   // 256 rows
    setup_kernel<<<24, 32>>>(
        (const float*)d_in[0],   // theta_am_0to1
        (const float*)d_in[1],   // theta_fm_0to1
        (const float*)d_in[2],   // phase
        (const float*)d_in[3],   // phase_am
        (const float*)d_in[4],   // phase_fm
        (const float*)d_in[5],   // u_am_mi
        (const float*)d_in[6],   // u_fm_hz
        (const float*)d_in[7],   // u_f0_hz
        B);
    amfm_main<<<B * CHUNKS, TPB>>>((float*)d_out);
}